// round 2
// baseline (speedup 1.0000x reference)
#include <cuda_runtime.h>

// Problem constants
#define MROWS 8192     // B*T
#define CD    256
#define FCD   1024
#define TD    1024
#define BD    8
#define HD_   64
#define NH    4
#define NL    6
#define NOUT  192
#define QBLK  4

// ---------------- scratch (device globals; no allocation allowed) ----------
__device__ float g_x[MROWS * CD];
__device__ float g_q[MROWS * CD];
__device__ float g_k[MROWS * CD];
__device__ float g_v[MROWS * CD];
__device__ float g_t[MROWS * CD];
__device__ float g_f[MROWS * FCD];

// ---------------- embedding ----------------
__global__ void embed_kernel(const float* __restrict__ emb,
                             const int* __restrict__ tok) {
    int idx = blockIdx.x * 256 + threadIdx.x;         // over MROWS*CD
    int m = idx >> 8;
    int c = idx & 255;
    g_x[idx] = emb[tok[m] * CD + c] * 16.0f;          // sqrt(256)
}

// ---------------- generic SGEMM: Y = A[MxK] @ W[KxN] + bias (opt relu) -----
__global__ __launch_bounds__(256)
void sgemm_bias(const float* __restrict__ A, const float* __restrict__ W,
                const float* __restrict__ bias, float* __restrict__ Y,
                int M, int N, int K, int relu) {
    __shared__ float As[8][128];
    __shared__ float Bs[8][128];
    int tid = threadIdx.x;
    int tx = tid & 15;        // 0..15  -> 8 cols each
    int ty = tid >> 4;        // 0..15  -> 8 rows each
    int rowBase = blockIdx.y * 128;
    int colBase = blockIdx.x * 128;
    float acc[8][8];
#pragma unroll
    for (int i = 0; i < 8; i++)
#pragma unroll
        for (int j = 0; j < 8; j++) acc[i][j] = 0.0f;

    for (int k0 = 0; k0 < K; k0 += 8) {
#pragma unroll
        for (int i = 0; i < 4; i++) {
            int e = tid + i * 256;          // 0..1023
            int r = e >> 3, kk = e & 7;
            As[kk][r] = A[(size_t)(rowBase + r) * K + k0 + kk];
        }
#pragma unroll
        for (int i = 0; i < 4; i++) {
            int e = tid + i * 256;
            int kk = e >> 7, cc = e & 127;
            Bs[kk][cc] = W[(size_t)(k0 + kk) * N + colBase + cc];
        }
        __syncthreads();
#pragma unroll
        for (int kk = 0; kk < 8; kk++) {
            float a[8], b[8];
#pragma unroll
            for (int i = 0; i < 8; i++) a[i] = As[kk][ty * 8 + i];
#pragma unroll
            for (int j = 0; j < 8; j++) b[j] = Bs[kk][tx * 8 + j];
#pragma unroll
            for (int i = 0; i < 8; i++)
#pragma unroll
                for (int j = 0; j < 8; j++) acc[i][j] += a[i] * b[j];
        }
        __syncthreads();
    }
#pragma unroll
    for (int i = 0; i < 8; i++) {
        int r = rowBase + ty * 8 + i;
#pragma unroll
        for (int j = 0; j < 8; j++) {
            int cc = colBase + tx * 8 + j;
            float v = acc[i][j] + bias[cc];
            if (relu) v = fmaxf(v, 0.0f);
            Y[(size_t)r * N + cc] = v;
        }
    }
}

// ---------------- fused attention (QBLK queries per block) -----------------
// q,k,v laid out [B,T,C]; head h uses columns [h*64, h*64+64).
__global__ __launch_bounds__(256)
void attn_kernel(const float* __restrict__ Q, const float* __restrict__ K,
                 const float* __restrict__ V, const float* __restrict__ relk,
                 const float* __restrict__ relv, const int* __restrict__ lens,
                 float* __restrict__ O) {
    int q0 = blockIdx.x * QBLK;
    int h  = blockIdx.y;
    int b  = blockIdx.z;
    int tid = threadIdx.x;   // 256

    __shared__ float sQ[QBLK][HD_];
    __shared__ float sS[QBLK][TD];
    __shared__ float sRed[8];
    __shared__ float sAcc[QBLK][4][HD_];

    int len = lens[b];

    if (tid < QBLK * HD_) {
        int qq = tid >> 6, d = tid & 63;
        sQ[qq][d] = Q[((size_t)(b * TD + q0 + qq) * CD) + h * HD_ + d] * 0.125f;
    }
    __syncthreads();

    const float* Kb = K + (size_t)b * TD * CD + h * HD_;
    // ---- scores ----
    for (int kk = tid; kk < TD; kk += 256) {
        const float4* kr = (const float4*)(Kb + (size_t)kk * CD);
        float acc[QBLK] = {0.f, 0.f, 0.f, 0.f};
#pragma unroll
        for (int i = 0; i < 16; i++) {
            float4 kv = kr[i];
#pragma unroll
            for (int qq = 0; qq < QBLK; qq++) {
                acc[qq] += sQ[qq][4 * i] * kv.x + sQ[qq][4 * i + 1] * kv.y +
                           sQ[qq][4 * i + 2] * kv.z + sQ[qq][4 * i + 3] * kv.w;
            }
        }
        bool kvalid = (kk < len);
#pragma unroll
        for (int qq = 0; qq < QBLK; qq++) {
            int qi = q0 + qq;
            float a = acc[qq];
            int r = kk - qi + 4;
            if ((unsigned)r <= 8u) {
                const float* rw = relk + r * HD_;
#pragma unroll
                for (int d = 0; d < HD_; d++) a += sQ[qq][d] * rw[d];
            }
            if (!(kvalid && (qi < len))) a = -10000.0f;
            sS[qq][kk] = a;
        }
    }
    __syncthreads();

    // ---- softmax per query row ----
    float invs[QBLK];
    for (int qq = 0; qq < QBLK; qq++) {
        float mx = -1e30f;
        for (int kk = tid; kk < TD; kk += 256) mx = fmaxf(mx, sS[qq][kk]);
#pragma unroll
        for (int off = 16; off > 0; off >>= 1)
            mx = fmaxf(mx, __shfl_xor_sync(0xffffffffu, mx, off));
        __syncthreads();                      // protect sRed from prev iter reads
        if ((tid & 31) == 0) sRed[tid >> 5] = mx;
        __syncthreads();
        mx = sRed[0];
#pragma unroll
        for (int i = 1; i < 8; i++) mx = fmaxf(mx, sRed[i]);

        float sm = 0.f;
        for (int kk = tid; kk < TD; kk += 256) {
            float e = __expf(sS[qq][kk] - mx);
            sS[qq][kk] = e;
            sm += e;
        }
#pragma unroll
        for (int off = 16; off > 0; off >>= 1)
            sm += __shfl_xor_sync(0xffffffffu, sm, off);
        __syncthreads();                      // all mx-reads done
        if ((tid & 31) == 0) sRed[tid >> 5] = sm;
        __syncthreads();
        float tot = 0.f;
#pragma unroll
        for (int i = 0; i < 8; i++) tot += sRed[i];
        invs[qq] = 1.0f / tot;
    }
    __syncthreads();

    // ---- P @ V (4 key-groups of 256 keys) ----
    {
        int d = tid & 63;
        int grp = tid >> 6;                   // 0..3
        const float* Vb = V + (size_t)b * TD * CD + h * HD_;
        float acc[QBLK] = {0.f, 0.f, 0.f, 0.f};
        int kbeg = grp * 256;
        for (int kk = kbeg; kk < kbeg + 256; kk++) {
            float vv = Vb[(size_t)kk * CD + d];
#pragma unroll
            for (int qq = 0; qq < QBLK; qq++) acc[qq] += sS[qq][kk] * vv;
        }
#pragma unroll
        for (int qq = 0; qq < QBLK; qq++) sAcc[qq][grp][d] = acc[qq];
    }
    __syncthreads();

    // ---- combine + rel_v + write ----
    {
        int qq = tid >> 6;
        int dd = tid & 63;
        float a = sAcc[qq][0][dd] + sAcc[qq][1][dd] + sAcc[qq][2][dd] + sAcc[qq][3][dd];
        float inv = invs[qq];
        a *= inv;
        int qi = q0 + qq;
        int k0 = qi - 4; if (k0 < 0) k0 = 0;
        int k1 = qi + 4; if (k1 > TD - 1) k1 = TD - 1;
        for (int k = k0; k <= k1; k++)
            a += sS[qq][k] * inv * relv[(k - qi + 4) * HD_ + dd];
        O[((size_t)(b * TD + qi) * CD) + h * HD_ + dd] = a;
    }
}

// ---------------- residual add + LayerNorm (optional length mask) ----------
__global__ __launch_bounds__(256)
void add_ln_kernel(const float* __restrict__ a, const float* __restrict__ r,
                   const float* __restrict__ g, const float* __restrict__ bb,
                   float* __restrict__ o, const int* __restrict__ lens,
                   int domask) {
    int m = blockIdx.x;
    int c = threadIdx.x;   // 256 = CD
    __shared__ float wsum[8], wsq[8];
    float v = a[(size_t)m * CD + c] + r[(size_t)m * CD + c];
    float s = v, q = v * v;
#pragma unroll
    for (int off = 16; off > 0; off >>= 1) {
        s += __shfl_xor_sync(0xffffffffu, s, off);
        q += __shfl_xor_sync(0xffffffffu, q, off);
    }
    if ((c & 31) == 0) { wsum[c >> 5] = s; wsq[c >> 5] = q; }
    __syncthreads();
    float S = 0.f, Qs = 0.f;
#pragma unroll
    for (int i = 0; i < 8; i++) { S += wsum[i]; Qs += wsq[i]; }
    float mean = S * (1.0f / CD);
    float var  = Qs * (1.0f / CD) - mean * mean;
    float inv = rsqrtf(var + 1e-5f);
    float out = (v - mean) * inv * g[c] + bb[c];
    if (domask) {
        int b = m >> 10, t = m & 1023;
        if (t >= lens[b]) out = 0.0f;
    }
    o[(size_t)m * CD + c] = out;
}

// ---------------- outputs ----------------
__global__ void xout_kernel(const float* __restrict__ x, float* __restrict__ ox) {
    __shared__ float tile[32][33];
    int t0 = blockIdx.x * 32, c0 = blockIdx.y * 32, b = blockIdx.z;
    int tx = threadIdx.x, ty = threadIdx.y;   // 32 x 8
    for (int i = ty; i < 32; i += 8)
        tile[i][tx] = x[((size_t)(b * TD + t0 + i) * CD) + c0 + tx];
    __syncthreads();
    for (int i = ty; i < 32; i += 8)
        ox[((size_t)(b * CD + c0 + i) * TD) + t0 + tx] = tile[tx][i];
}

__global__ void maskout_kernel(const int* __restrict__ lens, float* __restrict__ om) {
    int idx = blockIdx.x * 256 + threadIdx.x;  // over B*T
    int b = idx >> 10, t = idx & 1023;
    om[idx] = (t < lens[b]) ? 1.0f : 0.0f;
}

__global__ __launch_bounds__(384)
void stats_kernel(const float* __restrict__ x, const float* __restrict__ pw,
                  const float* __restrict__ pb, const int* __restrict__ lens,
                  float* __restrict__ om, float* __restrict__ ol) {
    int m = blockIdx.x;                 // 0..MROWS-1
    int b = m >> 10, t = m & 1023;
    __shared__ float sx[CD];
    int tid = threadIdx.x;              // 384
    if (tid < CD) sx[tid] = x[(size_t)m * CD + tid];
    __syncthreads();
    float msk = (t < lens[b]) ? 1.0f : 0.0f;
    const float4* w4 = (const float4*)(pw + (size_t)tid * CD);
    const float4* x4 = (const float4*)sx;
    float acc = 0.f;
#pragma unroll 16
    for (int i = 0; i < CD / 4; i++) {
        float4 w = w4[i], xv = x4[i];
        acc += w.x * xv.x + w.y * xv.y + w.z * xv.z + w.w * xv.w;
    }
    acc = (acc + pb[tid]) * msk;
    if (tid < NOUT) om[((size_t)b * NOUT + tid) * TD + t] = acc;
    else           ol[((size_t)b * NOUT + (tid - NOUT)) * TD + t] = acc;
}

// ---------------- launch ----------------
extern "C" void kernel_launch(void* const* d_in, const int* in_sizes, int n_in,
                              void* d_out, int out_size) {
    const float* emb  = (const float*)d_in[0];
    const float* Wq   = (const float*)d_in[1];
    const float* Wk   = (const float*)d_in[2];
    const float* Wv   = (const float*)d_in[3];
    const float* Wo   = (const float*)d_in[4];
    const float* bq   = (const float*)d_in[5];
    const float* bk   = (const float*)d_in[6];
    const float* bv   = (const float*)d_in[7];
    const float* bo   = (const float*)d_in[8];
    const float* relk = (const float*)d_in[9];
    const float* relv = (const float*)d_in[10];
    const float* ln1g = (const float*)d_in[11];
    const float* ln1b = (const float*)d_in[12];
    const float* ln2g = (const float*)d_in[13];
    const float* ln2b = (const float*)d_in[14];
    const float* fw1  = (const float*)d_in[15];
    const float* fb1  = (const float*)d_in[16];
    const float* fw2  = (const float*)d_in[17];
    const float* fb2  = (const float*)d_in[18];
    const float* pw   = (const float*)d_in[19];
    const float* pb   = (const float*)d_in[20];
    const int*   tok  = (const int*)d_in[21];
    const int*   lens = (const int*)d_in[22];

    float* out      = (float*)d_out;
    float* out_x    = out;
    float* out_m    = out_x + (size_t)BD * CD * TD;
    float* out_logs = out_m + (size_t)BD * NOUT * TD;
    float* out_mask = out_logs + (size_t)BD * NOUT * TD;

    float *px, *pq, *pk, *pv, *pt, *pf;
    cudaGetSymbolAddress((void**)&px, g_x);
    cudaGetSymbolAddress((void**)&pq, g_q);
    cudaGetSymbolAddress((void**)&pk, g_k);
    cudaGetSymbolAddress((void**)&pv, g_v);
    cudaGetSymbolAddress((void**)&pt, g_t);
    cudaGetSymbolAddress((void**)&pf, g_f);

    embed_kernel<<<MROWS * CD / 256, 256>>>(emb, tok);

    dim3 gC(CD / 128, MROWS / 128);       // N=256 GEMMs
    dim3 gF(FCD / 128, MROWS / 128);      // N=1024 GEMMs
    for (int i = 0; i < NL; i++) {
        const size_t wcc = (size_t)i * CD * CD;
        sgemm_bias<<<gC, 256>>>(px, Wq + wcc, bq + i * CD, pq, MROWS, CD, CD, 0);
        sgemm_bias<<<gC, 256>>>(px, Wk + wcc, bk + i * CD, pk, MROWS, CD, CD, 0);
        sgemm_bias<<<gC, 256>>>(px, Wv + wcc, bv + i * CD, pv, MROWS, CD, CD, 0);
        attn_kernel<<<dim3(TD / QBLK, NH, BD), 256>>>(
            pq, pk, pv, relk + (size_t)i * 9 * HD_, relv + (size_t)i * 9 * HD_,
            lens, pt);
        sgemm_bias<<<gC, 256>>>(pt, Wo + wcc, bo + i * CD, pq, MROWS, CD, CD, 0);
        add_ln_kernel<<<MROWS, 256>>>(px, pq, ln1g + i * CD, ln1b + i * CD, px, lens, 0);
        sgemm_bias<<<gF, 256>>>(px, fw1 + (size_t)i * CD * FCD, fb1 + i * FCD,
                                pf, MROWS, FCD, CD, 1);
        sgemm_bias<<<gC, 256>>>(pf, fw2 + (size_t)i * FCD * CD, fb2 + i * CD,
                                pt, MROWS, CD, FCD, 0);
        add_ln_kernel<<<MROWS, 256>>>(px, pt, ln2g + i * CD, ln2b + i * CD, px, lens, 1);
    }

    xout_kernel<<<dim3(TD / 32, CD / 32, BD), dim3(32, 8)>>>(px, out_x);
    maskout_kernel<<<BD * TD / 256, 256>>>(lens, out_mask);
    stats_kernel<<<MROWS, 384>>>(px, pw, pb, lens, out_m, out_logs);
}

// round 3
// speedup vs baseline: 2.0094x; 2.0094x over previous
#include <cuda_runtime.h>

// Problem constants
#define MROWS 8192     // B*T
#define CD    256
#define FCD   1024
#define TD    1024
#define BD    8
#define HD_   64
#define NH    4
#define NL    6
#define NOUT  192
#define QBLK  8

typedef unsigned long long ull;

// ---------------- f32x2 helpers (sm_103a packed fp32) ----------------------
__device__ __forceinline__ ull pack2(float lo, float hi) {
    ull d;
    asm("mov.b64 %0, {%1, %2};" : "=l"(d) : "f"(lo), "f"(hi));
    return d;
}
__device__ __forceinline__ float2 unpack2(ull v) {
    float lo, hi;
    asm("mov.b64 {%0, %1}, %2;" : "=f"(lo), "=f"(hi) : "l"(v));
    return make_float2(lo, hi);
}
__device__ __forceinline__ void fma2(ull& d, ull a, ull b) {
    asm("fma.rn.f32x2 %0, %1, %2, %0;" : "+l"(d) : "l"(a), "l"(b));
}

// ---------------- scratch (device globals; no allocation allowed) ----------
__device__ float g_x[MROWS * CD];
__device__ float g_q[MROWS * CD];
__device__ float g_k[MROWS * CD];
__device__ float g_v[MROWS * CD];
__device__ float g_t[MROWS * CD];
__device__ float g_f[MROWS * FCD];

// ---------------- embedding ----------------
__global__ void embed_kernel(const float* __restrict__ emb,
                             const int* __restrict__ tok) {
    int idx = blockIdx.x * 256 + threadIdx.x;         // over MROWS*CD
    int m = idx >> 8;
    int c = idx & 255;
    g_x[idx] = emb[tok[m] * CD + c] * 16.0f;          // sqrt(256)
}

// ---------------- SGEMM body: Y = A[MxK] @ W[KxN] + bias (opt relu) --------
// tile 128x64, 128 threads, 8x8 micro, K-step 16 double-buffered, f32x2 FMA.
__device__ __forceinline__
void gemm_body(const float* __restrict__ A, const float* __restrict__ W,
               const float* __restrict__ bias, float* __restrict__ Y,
               int N, int K, int relu)
{
    __shared__ float As[2][16][128];
    __shared__ float Bs[2][16][64];
    int tid = threadIdx.x;
    int tx = tid & 7, ty = tid >> 3;
    int rowBase = blockIdx.y * 128;
    int colBase = blockIdx.x * 64;
    const float* Arow = A + (size_t)(rowBase + tid) * K;
    int e0 = tid * 2, e1 = tid * 2 + 1;
    int bk0 = e0 >> 4, bc0 = e0 & 15;
    int bk1 = e1 >> 4, bc1 = e1 & 15;
    const float* Bp0 = W + (size_t)bk0 * N + colBase + bc0 * 4;
    const float* Bp1 = W + (size_t)bk1 * N + colBase + bc1 * 4;

    ull acc2[8][4];
#pragma unroll
    for (int i = 0; i < 8; i++)
#pragma unroll
        for (int j = 0; j < 4; j++) acc2[i][j] = 0ull;

    // prologue: tile 0
    {
        const float4* a4 = (const float4*)Arow;
#pragma unroll
        for (int i = 0; i < 4; i++) {
            float4 v = a4[i];
            As[0][4 * i + 0][tid] = v.x; As[0][4 * i + 1][tid] = v.y;
            As[0][4 * i + 2][tid] = v.z; As[0][4 * i + 3][tid] = v.w;
        }
        *(float4*)&Bs[0][bk0][bc0 * 4] = *(const float4*)Bp0;
        *(float4*)&Bs[0][bk1][bc1 * 4] = *(const float4*)Bp1;
    }
    __syncthreads();

    int nT = K >> 4;
    for (int t = 0; t < nT; t++) {
        int cur = t & 1;
        float4 ra[4], rb0, rb1;
        if (t + 1 < nT) {
            const float4* a4 = (const float4*)(Arow + (t + 1) * 16);
#pragma unroll
            for (int i = 0; i < 4; i++) ra[i] = a4[i];
            rb0 = *(const float4*)(Bp0 + (size_t)(t + 1) * 16 * N);
            rb1 = *(const float4*)(Bp1 + (size_t)(t + 1) * 16 * N);
        }
#pragma unroll
        for (int kk = 0; kk < 16; kk++) {
            float4 av0 = *(const float4*)&As[cur][kk][ty * 8];
            float4 av1 = *(const float4*)&As[cur][kk][ty * 8 + 4];
            ull bp0 = *(const ull*)&Bs[cur][kk][tx * 8];
            ull bp1 = *(const ull*)&Bs[cur][kk][tx * 8 + 2];
            ull bp2 = *(const ull*)&Bs[cur][kk][tx * 8 + 4];
            ull bp3 = *(const ull*)&Bs[cur][kk][tx * 8 + 6];
            float a[8] = {av0.x, av0.y, av0.z, av0.w, av1.x, av1.y, av1.z, av1.w};
#pragma unroll
            for (int i = 0; i < 8; i++) {
                ull ap = pack2(a[i], a[i]);
                fma2(acc2[i][0], ap, bp0);
                fma2(acc2[i][1], ap, bp1);
                fma2(acc2[i][2], ap, bp2);
                fma2(acc2[i][3], ap, bp3);
            }
        }
        if (t + 1 < nT) {
            int nxt = cur ^ 1;
#pragma unroll
            for (int i = 0; i < 4; i++) {
                As[nxt][4 * i + 0][tid] = ra[i].x; As[nxt][4 * i + 1][tid] = ra[i].y;
                As[nxt][4 * i + 2][tid] = ra[i].z; As[nxt][4 * i + 3][tid] = ra[i].w;
            }
            *(float4*)&Bs[nxt][bk0][bc0 * 4] = rb0;
            *(float4*)&Bs[nxt][bk1][bc1 * 4] = rb1;
        }
        __syncthreads();
    }

    float4 bi0 = *(const float4*)&bias[colBase + tx * 8];
    float4 bi1 = *(const float4*)&bias[colBase + tx * 8 + 4];
#pragma unroll
    for (int i = 0; i < 8; i++) {
        int r = rowBase + ty * 8 + i;
        float2 u0 = unpack2(acc2[i][0]);
        float2 u1 = unpack2(acc2[i][1]);
        float2 u2 = unpack2(acc2[i][2]);
        float2 u3 = unpack2(acc2[i][3]);
        float4 o0 = make_float4(u0.x + bi0.x, u0.y + bi0.y, u1.x + bi0.z, u1.y + bi0.w);
        float4 o1 = make_float4(u2.x + bi1.x, u2.y + bi1.y, u3.x + bi1.z, u3.y + bi1.w);
        if (relu) {
            o0.x = fmaxf(o0.x, 0.f); o0.y = fmaxf(o0.y, 0.f);
            o0.z = fmaxf(o0.z, 0.f); o0.w = fmaxf(o0.w, 0.f);
            o1.x = fmaxf(o1.x, 0.f); o1.y = fmaxf(o1.y, 0.f);
            o1.z = fmaxf(o1.z, 0.f); o1.w = fmaxf(o1.w, 0.f);
        }
        *(float4*)&Y[(size_t)r * N + colBase + tx * 8] = o0;
        *(float4*)&Y[(size_t)r * N + colBase + tx * 8 + 4] = o1;
    }
}

__global__ __launch_bounds__(128, 3)
void sgemm_k(const float* __restrict__ A, const float* __restrict__ W,
             const float* __restrict__ bias, float* __restrict__ Y,
             int N, int K, int relu) {
    gemm_body(A, W, bias, Y, N, K, relu);
}

// fused QKV: gridDim.z selects which projection
__global__ __launch_bounds__(128, 3)
void qkv_k(const float* __restrict__ A,
           const float* __restrict__ W0, const float* __restrict__ W1,
           const float* __restrict__ W2,
           const float* __restrict__ b0, const float* __restrict__ b1,
           const float* __restrict__ b2,
           float* __restrict__ Y0, float* __restrict__ Y1, float* __restrict__ Y2) {
    const float* W = (blockIdx.z == 0) ? W0 : (blockIdx.z == 1 ? W1 : W2);
    const float* bb = (blockIdx.z == 0) ? b0 : (blockIdx.z == 1 ? b1 : b2);
    float* Y = (blockIdx.z == 0) ? Y0 : (blockIdx.z == 1 ? Y1 : Y2);
    gemm_body(A, W, bb, Y, CD, CD, 0);
}

// ---------------- fused attention (QBLK=8 queries per block) ---------------
// dynamic smem layout: sQ[8*64] | sS[8*1024] | sAcc[8*16*64] | sRed[8]
#define ATTN_SMEM ((8 * 64 + 8 * 1024 + 8 * 16 * 64 + 8) * 4)

__global__ __launch_bounds__(256)
void attn_kernel(const float* __restrict__ Q, const float* __restrict__ K,
                 const float* __restrict__ V, const float* __restrict__ relk,
                 const float* __restrict__ relv, const int* __restrict__ lens,
                 float* __restrict__ O) {
    extern __shared__ float sm[];
    float* sQ = sm;                       // 512
    float* sS = sQ + 8 * 64;              // 8192
    float* sAcc = sS + 8 * 1024;          // 8192
    float* sRed = sAcc + 8 * 16 * 64;     // 8

    int q0 = blockIdx.x * QBLK;
    int h = blockIdx.y;
    int b = blockIdx.z;
    int tid = threadIdx.x;                // 256
    int len = lens[b];

    // load Q block (scaled)
    for (int i = tid; i < QBLK * HD_; i += 256) {
        int qq = i >> 6, d = i & 63;
        sQ[i] = Q[((size_t)(b * TD + q0 + qq) * CD) + h * HD_ + d] * 0.125f;
    }
    __syncthreads();

    const float* Kb = K + (size_t)b * TD * CD + h * HD_;
    // ---- scores: each thread owns 4 keys (tid + g*256), all 8 queries ----
    {
        ull acc2[QBLK][4];
#pragma unroll
        for (int qq = 0; qq < QBLK; qq++)
#pragma unroll
            for (int g = 0; g < 4; g++) acc2[qq][g] = 0ull;

        const float* k0p = Kb + (size_t)tid * CD;
#pragma unroll 4
        for (int d4 = 0; d4 < 16; d4++) {
            ulonglong2 kv[4];
#pragma unroll
            for (int g = 0; g < 4; g++)
                kv[g] = *(const ulonglong2*)(k0p + (size_t)g * 256 * CD + d4 * 4);
#pragma unroll
            for (int qq = 0; qq < QBLK; qq++) {
                ull qp0 = *(const ull*)&sQ[qq * 64 + d4 * 4];
                ull qp1 = *(const ull*)&sQ[qq * 64 + d4 * 4 + 2];
#pragma unroll
                for (int g = 0; g < 4; g++) {
                    fma2(acc2[qq][g], qp0, kv[g].x);
                    fma2(acc2[qq][g], qp1, kv[g].y);
                }
            }
        }
#pragma unroll
        for (int qq = 0; qq < QBLK; qq++) {
            int qi = q0 + qq;
            bool qv = (qi < len);
#pragma unroll
            for (int g = 0; g < 4; g++) {
                int kk = tid + g * 256;
                float2 u = unpack2(acc2[qq][g]);
                float s = u.x + u.y;
                int r = kk - qi + 4;
                if ((unsigned)r <= 8u) {
                    const float* rw = relk + r * HD_;
#pragma unroll
                    for (int d = 0; d < HD_; d++) s += sQ[qq * 64 + d] * rw[d];
                }
                if (!(qv && (kk < len))) s = -10000.0f;
                sS[qq * 1024 + kk] = s;
            }
        }
    }
    __syncthreads();

    // ---- softmax per query row ----
    float invs[QBLK];
    for (int qq = 0; qq < QBLK; qq++) {
        float mx = -1e30f;
        for (int kk = tid; kk < TD; kk += 256) mx = fmaxf(mx, sS[qq * 1024 + kk]);
#pragma unroll
        for (int off = 16; off > 0; off >>= 1)
            mx = fmaxf(mx, __shfl_xor_sync(0xffffffffu, mx, off));
        __syncthreads();
        if ((tid & 31) == 0) sRed[tid >> 5] = mx;
        __syncthreads();
        mx = sRed[0];
#pragma unroll
        for (int i = 1; i < 8; i++) mx = fmaxf(mx, sRed[i]);

        float smv = 0.f;
        for (int kk = tid; kk < TD; kk += 256) {
            float e = __expf(sS[qq * 1024 + kk] - mx);
            sS[qq * 1024 + kk] = e;
            smv += e;
        }
#pragma unroll
        for (int off = 16; off > 0; off >>= 1)
            smv += __shfl_xor_sync(0xffffffffu, smv, off);
        __syncthreads();
        if ((tid & 31) == 0) sRed[tid >> 5] = smv;
        __syncthreads();
        float tot = 0.f;
#pragma unroll
        for (int i = 0; i < 8; i++) tot += sRed[i];
        invs[qq] = 1.0f / tot;
    }
    __syncthreads();

    // ---- P @ V: 16 key-groups of 64 keys, float4 over dims ----
    {
        int grp = tid >> 4, d4i = tid & 15;
        const float* Vb = V + (size_t)b * TD * CD + h * HD_ + d4i * 4;
        ull pacc[QBLK][2];
#pragma unroll
        for (int qq = 0; qq < QBLK; qq++) { pacc[qq][0] = 0ull; pacc[qq][1] = 0ull; }
        int kbase = grp * 64;
#pragma unroll 4
        for (int kk = 0; kk < 64; kk++) {
            int key = kbase + kk;
            ulonglong2 vv = *(const ulonglong2*)(Vb + (size_t)key * CD);
#pragma unroll
            for (int qq = 0; qq < QBLK; qq++) {
                float p = sS[qq * 1024 + key];
                ull pd = pack2(p, p);
                fma2(pacc[qq][0], pd, vv.x);
                fma2(pacc[qq][1], pd, vv.y);
            }
        }
#pragma unroll
        for (int qq = 0; qq < QBLK; qq++) {
            float2 a0 = unpack2(pacc[qq][0]);
            float2 a1 = unpack2(pacc[qq][1]);
            *(float4*)&sAcc[(qq * 16 + grp) * 64 + d4i * 4] =
                make_float4(a0.x, a0.y, a1.x, a1.y);
        }
    }
    __syncthreads();

    // ---- combine + rel_v + write ----
    for (int it = tid; it < QBLK * HD_; it += 256) {
        int qq = it >> 6, dd = it & 63;
        float a = 0.f;
#pragma unroll
        for (int g = 0; g < 16; g++) a += sAcc[(qq * 16 + g) * 64 + dd];
        float inv = invs[qq];
        a *= inv;
        int qi = q0 + qq;
        int klo = qi - 4; if (klo < 0) klo = 0;
        int khi = qi + 4; if (khi > TD - 1) khi = TD - 1;
        for (int k = klo; k <= khi; k++)
            a += sS[qq * 1024 + k] * inv * relv[(k - qi + 4) * HD_ + dd];
        O[((size_t)(b * TD + qi) * CD) + h * HD_ + dd] = a;
    }
}

// ---------------- residual add + LayerNorm: warp per row -------------------
__global__ __launch_bounds__(256)
void add_ln_kernel(const float* __restrict__ a, const float* __restrict__ r,
                   const float* __restrict__ g, const float* __restrict__ bb,
                   float* __restrict__ o, const int* __restrict__ lens,
                   int domask) {
    int warp = threadIdx.x >> 5, lane = threadIdx.x & 31;
    int m = blockIdx.x * 8 + warp;
    const float4* a4 = (const float4*)(a + (size_t)m * CD);
    const float4* r4 = (const float4*)(r + (size_t)m * CD);
    float4 v0 = a4[lane * 2], v1 = a4[lane * 2 + 1];
    float4 w0 = r4[lane * 2], w1 = r4[lane * 2 + 1];
    v0.x += w0.x; v0.y += w0.y; v0.z += w0.z; v0.w += w0.w;
    v1.x += w1.x; v1.y += w1.y; v1.z += w1.z; v1.w += w1.w;
    float s = v0.x + v0.y + v0.z + v0.w + v1.x + v1.y + v1.z + v1.w;
    float q = v0.x * v0.x + v0.y * v0.y + v0.z * v0.z + v0.w * v0.w +
              v1.x * v1.x + v1.y * v1.y + v1.z * v1.z + v1.w * v1.w;
#pragma unroll
    for (int off = 16; off > 0; off >>= 1) {
        s += __shfl_xor_sync(0xffffffffu, s, off);
        q += __shfl_xor_sync(0xffffffffu, q, off);
    }
    float mean = s * (1.0f / CD);
    float var = q * (1.0f / CD) - mean * mean;
    float inv = rsqrtf(var + 1e-5f);
    float4 g0 = ((const float4*)g)[lane * 2], g1 = ((const float4*)g)[lane * 2 + 1];
    float4 b0 = ((const float4*)bb)[lane * 2], b1 = ((const float4*)bb)[lane * 2 + 1];
    float4 o0, o1;
    o0.x = (v0.x - mean) * inv * g0.x + b0.x;
    o0.y = (v0.y - mean) * inv * g0.y + b0.y;
    o0.z = (v0.z - mean) * inv * g0.z + b0.z;
    o0.w = (v0.w - mean) * inv * g0.w + b0.w;
    o1.x = (v1.x - mean) * inv * g1.x + b1.x;
    o1.y = (v1.y - mean) * inv * g1.y + b1.y;
    o1.z = (v1.z - mean) * inv * g1.z + b1.z;
    o1.w = (v1.w - mean) * inv * g1.w + b1.w;
    if (domask) {
        int bb2 = m >> 10, t = m & 1023;
        if (t >= lens[bb2]) {
            o0 = make_float4(0.f, 0.f, 0.f, 0.f);
            o1 = make_float4(0.f, 0.f, 0.f, 0.f);
        }
    }
    ((float4*)(o + (size_t)m * CD))[lane * 2] = o0;
    ((float4*)(o + (size_t)m * CD))[lane * 2 + 1] = o1;
}

// ---------------- outputs ----------------
__global__ void xout_kernel(const float* __restrict__ x, float* __restrict__ ox) {
    __shared__ float tile[32][33];
    int t0 = blockIdx.x * 32, c0 = blockIdx.y * 32, b = blockIdx.z;
    int tx = threadIdx.x, ty = threadIdx.y;   // 32 x 8
    for (int i = ty; i < 32; i += 8)
        tile[i][tx] = x[((size_t)(b * TD + t0 + i) * CD) + c0 + tx];
    __syncthreads();
    for (int i = ty; i < 32; i += 8)
        ox[((size_t)(b * CD + c0 + i) * TD) + t0 + tx] = tile[tx][i];
}

__global__ void maskout_kernel(const int* __restrict__ lens, float* __restrict__ om) {
    int idx = blockIdx.x * 256 + threadIdx.x;  // over B*T
    int b = idx >> 10, t = idx & 1023;
    om[idx] = (t < lens[b]) ? 1.0f : 0.0f;
}

// 8 tokens per block: weight rows re-read 8x less from L2
__global__ __launch_bounds__(384)
void stats_kernel(const float* __restrict__ x, const float* __restrict__ pw,
                  const float* __restrict__ pb, const int* __restrict__ lens,
                  float* __restrict__ om, float* __restrict__ ol) {
    int m0 = blockIdx.x * 8;
    __shared__ float sx[8][CD];
    int tid = threadIdx.x;              // 384
    for (int i = tid; i < 8 * CD / 4; i += 384)
        ((float4*)sx)[i] = ((const float4*)(x + (size_t)m0 * CD))[i];
    __syncthreads();

    float acc[8];
#pragma unroll
    for (int t = 0; t < 8; t++) acc[t] = 0.f;
    const float4* w4 = (const float4*)(pw + (size_t)tid * CD);
#pragma unroll 8
    for (int i = 0; i < CD / 4; i++) {
        float4 w = w4[i];
#pragma unroll
        for (int t = 0; t < 8; t++) {
            float4 xv = *(const float4*)&sx[t][i * 4];
            acc[t] += w.x * xv.x + w.y * xv.y + w.z * xv.z + w.w * xv.w;
        }
    }
    float bias = pb[tid];
#pragma unroll
    for (int t = 0; t < 8; t++) {
        int m = m0 + t;
        int b = m >> 10, tt = m & 1023;
        float msk = (tt < lens[b]) ? 1.0f : 0.0f;
        float val = (acc[t] + bias) * msk;
        if (tid < NOUT) om[((size_t)b * NOUT + tid) * TD + tt] = val;
        else            ol[((size_t)b * NOUT + (tid - NOUT)) * TD + tt] = val;
    }
}

// ---------------- launch ----------------
extern "C" void kernel_launch(void* const* d_in, const int* in_sizes, int n_in,
                              void* d_out, int out_size) {
    const float* emb  = (const float*)d_in[0];
    const float* Wq   = (const float*)d_in[1];
    const float* Wk   = (const float*)d_in[2];
    const float* Wv   = (const float*)d_in[3];
    const float* Wo   = (const float*)d_in[4];
    const float* bq   = (const float*)d_in[5];
    const float* bk   = (const float*)d_in[6];
    const float* bv   = (const float*)d_in[7];
    const float* bo   = (const float*)d_in[8];
    const float* relk = (const float*)d_in[9];
    const float* relv = (const float*)d_in[10];
    const float* ln1g = (const float*)d_in[11];
    const float* ln1b = (const float*)d_in[12];
    const float* ln2g = (const float*)d_in[13];
    const float* ln2b = (const float*)d_in[14];
    const float* fw1  = (const float*)d_in[15];
    const float* fb1  = (const float*)d_in[16];
    const float* fw2  = (const float*)d_in[17];
    const float* fb2  = (const float*)d_in[18];
    const float* pw   = (const float*)d_in[19];
    const float* pb   = (const float*)d_in[20];
    const int*   tok  = (const int*)d_in[21];
    const int*   lens = (const int*)d_in[22];

    float* out      = (float*)d_out;
    float* out_x    = out;
    float* out_m    = out_x + (size_t)BD * CD * TD;
    float* out_logs = out_m + (size_t)BD * NOUT * TD;
    float* out_mask = out_logs + (size_t)BD * NOUT * TD;

    float *px, *pq, *pk, *pv, *pt, *pf;
    cudaGetSymbolAddress((void**)&px, g_x);
    cudaGetSymbolAddress((void**)&pq, g_q);
    cudaGetSymbolAddress((void**)&pk, g_k);
    cudaGetSymbolAddress((void**)&pv, g_v);
    cudaGetSymbolAddress((void**)&pt, g_t);
    cudaGetSymbolAddress((void**)&pf, g_f);

    cudaFuncSetAttribute(attn_kernel,
                         cudaFuncAttributeMaxDynamicSharedMemorySize, ATTN_SMEM);

    embed_kernel<<<MROWS * CD / 256, 256>>>(emb, tok);

    dim3 gC(CD / 64, MROWS / 128);        // N=256 GEMMs: 256 blocks
    dim3 gQKV(CD / 64, MROWS / 128, 3);   // fused QKV: 768 blocks
    dim3 gF(FCD / 64, MROWS / 128);       // N=1024 GEMM: 1024 blocks
    for (int i = 0; i < NL; i++) {
        const size_t wcc = (size_t)i * CD * CD;
        qkv_k<<<gQKV, 128>>>(px, Wq + wcc, Wk + wcc, Wv + wcc,
                             bq + i * CD, bk + i * CD, bv + i * CD, pq, pk, pv);
        attn_kernel<<<dim3(TD / QBLK, NH, BD), 256, ATTN_SMEM>>>(
            pq, pk, pv, relk + (size_t)i * 9 * HD_, relv + (size_t)i * 9 * HD_,
            lens, pt);
        sgemm_k<<<gC, 128>>>(pt, Wo + wcc, bo + i * CD, pq, CD, CD, 0);
        add_ln_kernel<<<MROWS / 8, 256>>>(px, pq, ln1g + i * CD, ln1b + i * CD,
                                          px, lens, 0);
        sgemm_k<<<gF, 128>>>(px, fw1 + (size_t)i * CD * FCD, fb1 + i * FCD,
                             pf, FCD, CD, 1);
        sgemm_k<<<gC, 128>>>(pf, fw2 + (size_t)i * FCD * CD, fb2 + i * CD,
                             pt, CD, FCD, 0);
        add_ln_kernel<<<MROWS / 8, 256>>>(px, pt, ln2g + i * CD, ln2b + i * CD,
                                          px, lens, 1);
    }

    xout_kernel<<<dim3(TD / 32, CD / 32, BD), dim3(32, 8)>>>(px, out_x);
    maskout_kernel<<<BD * TD / 256, 256>>>(lens, out_mask);
    stats_kernel<<<MROWS / 8, 384>>>(px, pw, pb, lens, out_m, out_logs);
}

// round 4
// speedup vs baseline: 2.4381x; 1.2134x over previous
#include <cuda_runtime.h>

// Problem constants
#define MROWS 8192     // B*T
#define CD    256
#define FCD   1024
#define TD    1024
#define BD    8
#define HD_   64
#define NH    4
#define NL    6
#define NOUT  192
#define QB    16
#define ATHR  512

typedef unsigned long long ull;

// ---------------- f32x2 helpers (sm_103a packed fp32) ----------------------
__device__ __forceinline__ ull pack2(float lo, float hi) {
    ull d;
    asm("mov.b64 %0, {%1, %2};" : "=l"(d) : "f"(lo), "f"(hi));
    return d;
}
__device__ __forceinline__ float2 unpack2(ull v) {
    float lo, hi;
    asm("mov.b64 {%0, %1}, %2;" : "=f"(lo), "=f"(hi) : "l"(v));
    return make_float2(lo, hi);
}
__device__ __forceinline__ void fma2(ull& d, ull a, ull b) {
    asm("fma.rn.f32x2 %0, %1, %2, %0;" : "+l"(d) : "l"(a), "l"(b));
}

// ---------------- scratch (device globals; no allocation allowed) ----------
__device__ float g_x[MROWS * CD];
__device__ float g_q[MROWS * CD];
__device__ float g_k[MROWS * CD];
__device__ float g_v[MROWS * CD];
__device__ float g_t[MROWS * CD];
__device__ float g_f[MROWS * FCD];

// ---------------- embedding ----------------
__global__ void embed_kernel(const float* __restrict__ emb,
                             const int* __restrict__ tok) {
    int idx = blockIdx.x * 256 + threadIdx.x;         // over MROWS*CD
    int m = idx >> 8;
    int c = idx & 255;
    g_x[idx] = emb[tok[m] * CD + c] * 16.0f;          // sqrt(256)
}

// ---------------- SGEMM body: Y = A[MxK] @ W[KxN] + bias (opt relu) --------
// tile 128x64, 128 threads, 8x8 micro, K-step 16 double-buffered, f32x2 FMA.
__device__ __forceinline__
void gemm_body(const float* __restrict__ A, const float* __restrict__ W,
               const float* __restrict__ bias, float* __restrict__ Y,
               int N, int K, int relu)
{
    __shared__ float As[2][16][128];
    __shared__ float Bs[2][16][64];
    int tid = threadIdx.x;
    int tx = tid & 7, ty = tid >> 3;
    int rowBase = blockIdx.y * 128;
    int colBase = blockIdx.x * 64;
    const float* Arow = A + (size_t)(rowBase + tid) * K;
    int e0 = tid * 2, e1 = tid * 2 + 1;
    int bk0 = e0 >> 4, bc0 = e0 & 15;
    int bk1 = e1 >> 4, bc1 = e1 & 15;
    const float* Bp0 = W + (size_t)bk0 * N + colBase + bc0 * 4;
    const float* Bp1 = W + (size_t)bk1 * N + colBase + bc1 * 4;

    ull acc2[8][4];
#pragma unroll
    for (int i = 0; i < 8; i++)
#pragma unroll
        for (int j = 0; j < 4; j++) acc2[i][j] = 0ull;

    // prologue: tile 0
    {
        const float4* a4 = (const float4*)Arow;
#pragma unroll
        for (int i = 0; i < 4; i++) {
            float4 v = a4[i];
            As[0][4 * i + 0][tid] = v.x; As[0][4 * i + 1][tid] = v.y;
            As[0][4 * i + 2][tid] = v.z; As[0][4 * i + 3][tid] = v.w;
        }
        *(float4*)&Bs[0][bk0][bc0 * 4] = *(const float4*)Bp0;
        *(float4*)&Bs[0][bk1][bc1 * 4] = *(const float4*)Bp1;
    }
    __syncthreads();

    int nT = K >> 4;
    for (int t = 0; t < nT; t++) {
        int cur = t & 1;
        float4 ra[4], rb0, rb1;
        if (t + 1 < nT) {
            const float4* a4 = (const float4*)(Arow + (t + 1) * 16);
#pragma unroll
            for (int i = 0; i < 4; i++) ra[i] = a4[i];
            rb0 = *(const float4*)(Bp0 + (size_t)(t + 1) * 16 * N);
            rb1 = *(const float4*)(Bp1 + (size_t)(t + 1) * 16 * N);
        }
#pragma unroll
        for (int kk = 0; kk < 16; kk++) {
            float4 av0 = *(const float4*)&As[cur][kk][ty * 8];
            float4 av1 = *(const float4*)&As[cur][kk][ty * 8 + 4];
            ull bp0 = *(const ull*)&Bs[cur][kk][tx * 8];
            ull bp1 = *(const ull*)&Bs[cur][kk][tx * 8 + 2];
            ull bp2 = *(const ull*)&Bs[cur][kk][tx * 8 + 4];
            ull bp3 = *(const ull*)&Bs[cur][kk][tx * 8 + 6];
            float a[8] = {av0.x, av0.y, av0.z, av0.w, av1.x, av1.y, av1.z, av1.w};
#pragma unroll
            for (int i = 0; i < 8; i++) {
                ull ap = pack2(a[i], a[i]);
                fma2(acc2[i][0], ap, bp0);
                fma2(acc2[i][1], ap, bp1);
                fma2(acc2[i][2], ap, bp2);
                fma2(acc2[i][3], ap, bp3);
            }
        }
        if (t + 1 < nT) {
            int nxt = cur ^ 1;
#pragma unroll
            for (int i = 0; i < 4; i++) {
                As[nxt][4 * i + 0][tid] = ra[i].x; As[nxt][4 * i + 1][tid] = ra[i].y;
                As[nxt][4 * i + 2][tid] = ra[i].z; As[nxt][4 * i + 3][tid] = ra[i].w;
            }
            *(float4*)&Bs[nxt][bk0][bc0 * 4] = rb0;
            *(float4*)&Bs[nxt][bk1][bc1 * 4] = rb1;
        }
        __syncthreads();
    }

    float4 bi0 = *(const float4*)&bias[colBase + tx * 8];
    float4 bi1 = *(const float4*)&bias[colBase + tx * 8 + 4];
#pragma unroll
    for (int i = 0; i < 8; i++) {
        int r = rowBase + ty * 8 + i;
        float2 u0 = unpack2(acc2[i][0]);
        float2 u1 = unpack2(acc2[i][1]);
        float2 u2 = unpack2(acc2[i][2]);
        float2 u3 = unpack2(acc2[i][3]);
        float4 o0 = make_float4(u0.x + bi0.x, u0.y + bi0.y, u1.x + bi0.z, u1.y + bi0.w);
        float4 o1 = make_float4(u2.x + bi1.x, u2.y + bi1.y, u3.x + bi1.z, u3.y + bi1.w);
        if (relu) {
            o0.x = fmaxf(o0.x, 0.f); o0.y = fmaxf(o0.y, 0.f);
            o0.z = fmaxf(o0.z, 0.f); o0.w = fmaxf(o0.w, 0.f);
            o1.x = fmaxf(o1.x, 0.f); o1.y = fmaxf(o1.y, 0.f);
            o1.z = fmaxf(o1.z, 0.f); o1.w = fmaxf(o1.w, 0.f);
        }
        *(float4*)&Y[(size_t)r * N + colBase + tx * 8] = o0;
        *(float4*)&Y[(size_t)r * N + colBase + tx * 8 + 4] = o1;
    }
}

__global__ __launch_bounds__(128, 3)
void sgemm_k(const float* __restrict__ A, const float* __restrict__ W,
             const float* __restrict__ bias, float* __restrict__ Y,
             int N, int K, int relu) {
    gemm_body(A, W, bias, Y, N, K, relu);
}

// fused QKV: gridDim.z selects which projection
__global__ __launch_bounds__(128, 3)
void qkv_k(const float* __restrict__ A,
           const float* __restrict__ W0, const float* __restrict__ W1,
           const float* __restrict__ W2,
           const float* __restrict__ b0, const float* __restrict__ b1,
           const float* __restrict__ b2,
           float* __restrict__ Y0, float* __restrict__ Y1, float* __restrict__ Y2) {
    const float* W = (blockIdx.z == 0) ? W0 : (blockIdx.z == 1 ? W1 : W2);
    const float* bb = (blockIdx.z == 0) ? b0 : (blockIdx.z == 1 ? b1 : b2);
    float* Y = (blockIdx.z == 0) ? Y0 : (blockIdx.z == 1 ? Y1 : Y2);
    gemm_body(A, W, bb, Y, CD, CD, 0);
}

// ---------------- fused attention (QB=16 queries per block, 512 thr) -------
// smem floats: sQ 1024 | sRelK 192 | sPart 256 | sInv 16 | sDiag 160 | sS 16384
#define ATTN_SMEM ((1024 + 192 + 256 + 16 + 160 + 16384) * 4)

__global__ __launch_bounds__(ATHR, 1)
void attn_kernel(const float* __restrict__ Q, const float* __restrict__ K,
                 const float* __restrict__ V, const float* __restrict__ relk,
                 const float* __restrict__ relv, const int* __restrict__ lens,
                 float* __restrict__ O) {
    extern __shared__ float sm[];
    float* sQ    = sm;                  // 16*64
    float* sRelK = sQ + QB * HD_;       // 16*12 (9 used, padded)
    float* sPart = sRelK + QB * 12;     // 16*16
    float* sInv  = sPart + 256;         // 16
    float* sDiag = sInv + 16;           // 16*9 (+pad to 160)
    float* sS    = sDiag + 160;         // 16*1024; later aliased as sAcc[16][16][64]

    int tid = threadIdx.x;              // 512
    int q0 = blockIdx.x * QB;
    int h  = blockIdx.y;
    int b  = blockIdx.z;
    int len = lens[b];

    // ---- load Q (scaled) ----
    for (int i = tid; i < QB * HD_; i += ATHR) {
        int qq = i >> 6, d = i & 63;
        sQ[i] = Q[((size_t)(b * TD + q0 + qq) * CD) + h * HD_ + d] * 0.125f;
    }
    __syncthreads();

    // ---- precompute q . rel_k for the 9 diagonals ----
    if (tid < QB * 9) {
        int qq = tid / 9, r = tid % 9;
        const float* rw = relk + r * HD_;
        float s = 0.f;
#pragma unroll
        for (int d = 0; d < HD_; d++) s += sQ[qq * HD_ + d] * rw[d];
        sRelK[qq * 12 + r] = s;
    }
    __syncthreads();

    // ---- scores + fused exp + partial row sums ----
    {
        const float* Kb = K + (size_t)b * TD * CD + h * HD_;
        ull acc[2][QB];
#pragma unroll
        for (int g = 0; g < 2; g++)
#pragma unroll
            for (int qq = 0; qq < QB; qq++) acc[g][qq] = 0ull;

        const float* kp0 = Kb + (size_t)tid * CD;
        const float* kp1 = Kb + (size_t)(tid + 512) * CD;
#pragma unroll 4
        for (int d4 = 0; d4 < 16; d4++) {
            ulonglong2 kv0 = *(const ulonglong2*)(kp0 + d4 * 4);
            ulonglong2 kv1 = *(const ulonglong2*)(kp1 + d4 * 4);
#pragma unroll
            for (int qq = 0; qq < QB; qq++) {
                ull qp0 = *(const ull*)&sQ[qq * HD_ + d4 * 4];
                ull qp1 = *(const ull*)&sQ[qq * HD_ + d4 * 4 + 2];
                fma2(acc[0][qq], qp0, kv0.x);
                fma2(acc[0][qq], qp1, kv0.y);
                fma2(acc[1][qq], qp0, kv1.x);
                fma2(acc[1][qq], qp1, kv1.y);
            }
        }

        float psum[QB];
#pragma unroll
        for (int qq = 0; qq < QB; qq++) psum[qq] = 0.f;
#pragma unroll
        for (int g = 0; g < 2; g++) {
            int key = tid + g * 512;
            bool kok = key < len;
#pragma unroll
            for (int qq = 0; qq < QB; qq++) {
                float2 u = unpack2(acc[g][qq]);
                float s = u.x + u.y;
                int r = key - (q0 + qq) + 4;
                if ((unsigned)r <= 8u) s += sRelK[qq * 12 + r];
                float e = (kok && (q0 + qq) < len) ? __expf(s) : 0.f;
                sS[qq * TD + key] = e;
                psum[qq] += e;
            }
        }
        int lane = tid & 31, warp = tid >> 5;
#pragma unroll
        for (int qq = 0; qq < QB; qq++) {
            float v = psum[qq];
#pragma unroll
            for (int off = 16; off > 0; off >>= 1)
                v += __shfl_xor_sync(0xffffffffu, v, off);
            if (lane == 0) sPart[qq * 16 + warp] = v;
        }
    }
    __syncthreads();

    // ---- finalize inverse sums + save diagonal probs (for rel_v) ----
    if (tid < QB) {
        float s = 0.f;
#pragma unroll
        for (int w = 0; w < 16; w++) s += sPart[tid * 16 + w];
        sInv[tid] = (s > 0.f) ? 1.0f / s : 0.f;
    }
    if (tid >= 64 && tid < 64 + QB * 9) {
        int t2 = tid - 64;
        int qq = t2 / 9, r = t2 % 9;
        int k = q0 + qq + r - 4;
        sDiag[qq * 9 + r] = (k >= 0 && k < TD) ? sS[qq * TD + k] : 0.f;
    }
    __syncthreads();

    // ---- P @ V: 16 warps x 64 keys, lane owns 2 dims (f32x2) ----
    {
        int grp = tid >> 5, lane = tid & 31;
        const float* Vb = V + (size_t)b * TD * CD + h * HD_ + lane * 2;
        ull acc[QB];
#pragma unroll
        for (int qq = 0; qq < QB; qq++) acc[qq] = 0ull;
        int kbase = grp * 64;
#pragma unroll 2
        for (int kk = 0; kk < 64; kk++) {
            int key = kbase + kk;
            ull vv = *(const ull*)(Vb + (size_t)key * CD);
#pragma unroll
            for (int qq = 0; qq < QB; qq++) {
                float p = sS[qq * TD + key];
                fma2(acc[qq], pack2(p, p), vv);
            }
        }
        __syncthreads();   // all sS reads complete before aliasing as sAcc
#pragma unroll
        for (int qq = 0; qq < QB; qq++)
            *(ull*)&sS[(grp * 16 + qq) * 64 + lane * 2] = acc[qq];
    }
    __syncthreads();

    // ---- combine groups + rel_v + write ----
    for (int i = tid; i < QB * HD_; i += ATHR) {
        int qq = i >> 6, dd = i & 63;
        float a = 0.f;
#pragma unroll
        for (int g = 0; g < 16; g++) a += sS[(g * 16 + qq) * 64 + dd];
        float inv = sInv[qq];
        a *= inv;
#pragma unroll
        for (int r = 0; r < 9; r++)
            a += sDiag[qq * 9 + r] * inv * relv[r * HD_ + dd];
        O[((size_t)(b * TD + q0 + qq) * CD) + h * HD_ + dd] = a;
    }
}

// ---------------- residual add + LayerNorm: warp per row -------------------
__global__ __launch_bounds__(256)
void add_ln_kernel(const float* __restrict__ a, const float* __restrict__ r,
                   const float* __restrict__ g, const float* __restrict__ bb,
                   float* __restrict__ o, const int* __restrict__ lens,
                   int domask) {
    int warp = threadIdx.x >> 5, lane = threadIdx.x & 31;
    int m = blockIdx.x * 8 + warp;
    const float4* a4 = (const float4*)(a + (size_t)m * CD);
    const float4* r4 = (const float4*)(r + (size_t)m * CD);
    float4 v0 = a4[lane * 2], v1 = a4[lane * 2 + 1];
    float4 w0 = r4[lane * 2], w1 = r4[lane * 2 + 1];
    v0.x += w0.x; v0.y += w0.y; v0.z += w0.z; v0.w += w0.w;
    v1.x += w1.x; v1.y += w1.y; v1.z += w1.z; v1.w += w1.w;
    float s = v0.x + v0.y + v0.z + v0.w + v1.x + v1.y + v1.z + v1.w;
    float q = v0.x * v0.x + v0.y * v0.y + v0.z * v0.z + v0.w * v0.w +
              v1.x * v1.x + v1.y * v1.y + v1.z * v1.z + v1.w * v1.w;
#pragma unroll
    for (int off = 16; off > 0; off >>= 1) {
        s += __shfl_xor_sync(0xffffffffu, s, off);
        q += __shfl_xor_sync(0xffffffffu, q, off);
    }
    float mean = s * (1.0f / CD);
    float var = q * (1.0f / CD) - mean * mean;
    float inv = rsqrtf(var + 1e-5f);
    float4 g0 = ((const float4*)g)[lane * 2], g1 = ((const float4*)g)[lane * 2 + 1];
    float4 b0 = ((const float4*)bb)[lane * 2], b1 = ((const float4*)bb)[lane * 2 + 1];
    float4 o0, o1;
    o0.x = (v0.x - mean) * inv * g0.x + b0.x;
    o0.y = (v0.y - mean) * inv * g0.y + b0.y;
    o0.z = (v0.z - mean) * inv * g0.z + b0.z;
    o0.w = (v0.w - mean) * inv * g0.w + b0.w;
    o1.x = (v1.x - mean) * inv * g1.x + b1.x;
    o1.y = (v1.y - mean) * inv * g1.y + b1.y;
    o1.z = (v1.z - mean) * inv * g1.z + b1.z;
    o1.w = (v1.w - mean) * inv * g1.w + b1.w;
    if (domask) {
        int bb2 = m >> 10, t = m & 1023;
        if (t >= lens[bb2]) {
            o0 = make_float4(0.f, 0.f, 0.f, 0.f);
            o1 = make_float4(0.f, 0.f, 0.f, 0.f);
        }
    }
    ((float4*)(o + (size_t)m * CD))[lane * 2] = o0;
    ((float4*)(o + (size_t)m * CD))[lane * 2 + 1] = o1;
}

// ---------------- outputs ----------------
__global__ void xout_kernel(const float* __restrict__ x, float* __restrict__ ox) {
    __shared__ float tile[32][33];
    int t0 = blockIdx.x * 32, c0 = blockIdx.y * 32, b = blockIdx.z;
    int tx = threadIdx.x, ty = threadIdx.y;   // 32 x 8
    for (int i = ty; i < 32; i += 8)
        tile[i][tx] = x[((size_t)(b * TD + t0 + i) * CD) + c0 + tx];
    __syncthreads();
    for (int i = ty; i < 32; i += 8)
        ox[((size_t)(b * CD + c0 + i) * TD) + t0 + tx] = tile[tx][i];
}

__global__ void maskout_kernel(const int* __restrict__ lens, float* __restrict__ om) {
    int idx = blockIdx.x * 256 + threadIdx.x;  // over B*T
    int b = idx >> 10, t = idx & 1023;
    om[idx] = (t < lens[b]) ? 1.0f : 0.0f;
}

// 8 tokens per block: weight rows re-read 8x less from L2
__global__ __launch_bounds__(384)
void stats_kernel(const float* __restrict__ x, const float* __restrict__ pw,
                  const float* __restrict__ pb, const int* __restrict__ lens,
                  float* __restrict__ om, float* __restrict__ ol) {
    int m0 = blockIdx.x * 8;
    __shared__ float sx[8][CD];
    int tid = threadIdx.x;              // 384
    for (int i = tid; i < 8 * CD / 4; i += 384)
        ((float4*)sx)[i] = ((const float4*)(x + (size_t)m0 * CD))[i];
    __syncthreads();

    float acc[8];
#pragma unroll
    for (int t = 0; t < 8; t++) acc[t] = 0.f;
    const float4* w4 = (const float4*)(pw + (size_t)tid * CD);
#pragma unroll 8
    for (int i = 0; i < CD / 4; i++) {
        float4 w = w4[i];
#pragma unroll
        for (int t = 0; t < 8; t++) {
            float4 xv = *(const float4*)&sx[t][i * 4];
            acc[t] += w.x * xv.x + w.y * xv.y + w.z * xv.z + w.w * xv.w;
        }
    }
    float bias = pb[tid];
#pragma unroll
    for (int t = 0; t < 8; t++) {
        int m = m0 + t;
        int b = m >> 10, tt = m & 1023;
        float msk = (tt < lens[b]) ? 1.0f : 0.0f;
        float val = (acc[t] + bias) * msk;
        if (tid < NOUT) om[((size_t)b * NOUT + tid) * TD + tt] = val;
        else            ol[((size_t)b * NOUT + (tid - NOUT)) * TD + tt] = val;
    }
}

// ---------------- launch ----------------
extern "C" void kernel_launch(void* const* d_in, const int* in_sizes, int n_in,
                              void* d_out, int out_size) {
    const float* emb  = (const float*)d_in[0];
    const float* Wq   = (const float*)d_in[1];
    const float* Wk   = (const float*)d_in[2];
    const float* Wv   = (const float*)d_in[3];
    const float* Wo   = (const float*)d_in[4];
    const float* bq   = (const float*)d_in[5];
    const float* bk   = (const float*)d_in[6];
    const float* bv   = (const float*)d_in[7];
    const float* bo   = (const float*)d_in[8];
    const float* relk = (const float*)d_in[9];
    const float* relv = (const float*)d_in[10];
    const float* ln1g = (const float*)d_in[11];
    const float* ln1b = (const float*)d_in[12];
    const float* ln2g = (const float*)d_in[13];
    const float* ln2b = (const float*)d_in[14];
    const float* fw1  = (const float*)d_in[15];
    const float* fb1  = (const float*)d_in[16];
    const float* fw2  = (const float*)d_in[17];
    const float* fb2  = (const float*)d_in[18];
    const float* pw   = (const float*)d_in[19];
    const float* pb   = (const float*)d_in[20];
    const int*   tok  = (const int*)d_in[21];
    const int*   lens = (const int*)d_in[22];

    float* out      = (float*)d_out;
    float* out_x    = out;
    float* out_m    = out_x + (size_t)BD * CD * TD;
    float* out_logs = out_m + (size_t)BD * NOUT * TD;
    float* out_mask = out_logs + (size_t)BD * NOUT * TD;

    float *px, *pq, *pk, *pv, *pt, *pf;
    cudaGetSymbolAddress((void**)&px, g_x);
    cudaGetSymbolAddress((void**)&pq, g_q);
    cudaGetSymbolAddress((void**)&pk, g_k);
    cudaGetSymbolAddress((void**)&pv, g_v);
    cudaGetSymbolAddress((void**)&pt, g_t);
    cudaGetSymbolAddress((void**)&pf, g_f);

    cudaFuncSetAttribute(attn_kernel,
                         cudaFuncAttributeMaxDynamicSharedMemorySize, ATTN_SMEM);

    embed_kernel<<<MROWS * CD / 256, 256>>>(emb, tok);

    dim3 gC(CD / 64, MROWS / 128);        // N=256 GEMMs: 256 blocks
    dim3 gQKV(CD / 64, MROWS / 128, 3);   // fused QKV: 768 blocks
    dim3 gF(FCD / 64, MROWS / 128);       // N=1024 GEMM: 1024 blocks
    for (int i = 0; i < NL; i++) {
        const size_t wcc = (size_t)i * CD * CD;
        qkv_k<<<gQKV, 128>>>(px, Wq + wcc, Wk + wcc, Wv + wcc,
                             bq + i * CD, bk + i * CD, bv + i * CD, pq, pk, pv);
        attn_kernel<<<dim3(TD / QB, NH, BD), ATHR, ATTN_SMEM>>>(
            pq, pk, pv, relk + (size_t)i * 9 * HD_, relv + (size_t)i * 9 * HD_,
            lens, pt);
        sgemm_k<<<gC, 128>>>(pt, Wo + wcc, bo + i * CD, pq, CD, CD, 0);
        add_ln_kernel<<<MROWS / 8, 256>>>(px, pq, ln1g + i * CD, ln1b + i * CD,
                                          px, lens, 0);
        sgemm_k<<<gF, 128>>>(px, fw1 + (size_t)i * CD * FCD, fb1 + i * FCD,
                             pf, FCD, CD, 1);
        sgemm_k<<<gC, 128>>>(pf, fw2 + (size_t)i * FCD * CD, fb2 + i * CD,
                             pt, CD, FCD, 0);
        add_ln_kernel<<<MROWS / 8, 256>>>(px, pt, ln2g + i * CD, ln2b + i * CD,
                                          px, lens, 1);
    }

    xout_kernel<<<dim3(TD / 32, CD / 32, BD), dim3(32, 8)>>>(px, out_x);
    maskout_kernel<<<BD * TD / 256, 256>>>(lens, out_mask);
    stats_kernel<<<MROWS / 8, 384>>>(px, pw, pb, lens, out_m, out_logs);
}